// round 6
// baseline (speedup 1.0000x reference)
#include <cuda_runtime.h>
#include <cstdint>
#include <math.h>

#define NN 8192
#define EPSF 1e-20f
#define NITER 32
#define NCTA 148
#define NTHR 512
#define ROWB 32768               // bytes per H row
#define RDEPTH 6                 // TMA ring slots

// dynamic smem layout
#define SM_MBAR 0                // 6 mbarriers, 16B stride
#define SM_WRED 128              // 2 x 16 warp partials (double-buffered)
#define SM_GPART 1024            // 512 floats (phase-B group partials)
#define SM_SRED 3072             // 64 floats (phase-B rs partials)
#define SM_T    3328             // 56 floats: this CTA's t_r = (Hp)_row
#define SM_QH   3584             // 56 floats: incremental q_hat for own rows
#define SM_RING 4096             // RDEPTH x 32768 row buffers
#define SMEM_TOTAL (SM_RING + RDEPTH * ROWB)

// ---- device scratch (no allocations allowed) ----
__device__ float g_slab[NCTA * NN];     // 4.85 MB per-CTA Ap partial slabs
__device__ float g_ttpart[NCTA];
__device__ float g_rspart[NCTA];
__device__ float g_r[NN], g_p[NN], g_v[NN], g_qh[NN];
__device__ float g_mpart[64 * 8];
__device__ float g_fftsum[8];
__device__ unsigned g_flags[NCTA];      // grid-barrier flags (monotone across replays)

// ---------------- PTX helpers ----------------
__device__ __forceinline__ uint32_t sm_u32(const void* p) {
    uint32_t a;
    asm("{ .reg .u64 t; cvta.to.shared.u64 t, %1; cvt.u32.u64 %0, t; }" : "=r"(a) : "l"(p));
    return a;
}
#define MB_INIT(a, c) \
    asm volatile("mbarrier.init.shared.b64 [%0], %1;" :: "r"(a), "r"(c) : "memory")
#define MB_EXPECT(a, b) \
    asm volatile("mbarrier.arrive.expect_tx.shared.b64 _, [%0], %1;" :: "r"(a), "r"(b) : "memory")
#define BULK_LD(dst, src, sz, mb) \
    asm volatile("cp.async.bulk.shared::cta.global.mbarrier::complete_tx::bytes [%0], [%1], %2, [%3];" \
                 :: "r"(dst), "l"(src), "r"(sz), "r"(mb) : "memory")

__device__ __forceinline__ void mb_wait(uint32_t mbar, uint32_t parity) {
    uint32_t done;
    do {
        asm volatile("{ .reg .pred p; mbarrier.try_wait.parity.acquire.cta.shared::cta.b64 p, [%1], %2; "
                     "selp.b32 %0, 1, 0, p; }" : "=r"(done) : "r"(mbar), "r"(parity) : "memory");
    } while (!done);
}

__device__ __forceinline__ void grid_bar(int tid, int bid, unsigned gen) {
    __syncthreads();
    if (tid == 0)
        asm volatile("st.global.release.gpu.u32 [%0], %1;" :: "l"(&g_flags[bid]), "r"(gen) : "memory");
    if (tid < NCTA) {
        unsigned v;
        do {
            asm volatile("ld.global.acquire.gpu.u32 %0, [%1];" : "=r"(v) : "l"(&g_flags[tid]) : "memory");
        } while ((int)(v - gen) < 0);
    }
    __syncthreads();
}

// ---------------------------------------------------------------------------
// One streaming pass over this CTA's rows via the TMA ring.
// MODE 0: tr = dot(row, preg) -> apa += tr*row, ta += tr*tr, smem t[r] = tr
// MODE 1: tr = xvec[row]      -> apa += tr*row                (setup b = H^T x)
// ---------------------------------------------------------------------------
template<int MODE>
__device__ __forceinline__ float run_pass(const float* __restrict__ H, char* smem,
                                          uint32_t smb, int tid, int row0, int nrows,
                                          unsigned& gq, const float4* preg, float4* apa,
                                          const float* __restrict__ xvec) {
    float* wred = (float*)(smem + SM_WRED);
    float* smt  = (float*)(smem + SM_T);
#pragma unroll
    for (int c = 0; c < 4; c++) apa[c] = make_float4(0.f, 0.f, 0.f, 0.f);
    float ta = 0.f;
    if (tid == 0) {
        int npro = nrows < RDEPTH ? nrows : RDEPTH;
        for (int k = 0; k < npro; k++) {
            unsigned u = gq + k;
            uint32_t slot = u % RDEPTH;
            uint32_t mb = smb + SM_MBAR + slot * 16;
            MB_EXPECT(mb, ROWB);
            BULK_LD(smb + SM_RING + slot * ROWB,
                    (const void*)(H + (size_t)(row0 + k) * NN), (uint32_t)ROWB, mb);
        }
    }
    for (int r = 0; r < nrows; r++) {
        unsigned u = gq + r;
        uint32_t slot = u % RDEPTH;
        mb_wait(smb + SM_MBAR + slot * 16, (u / RDEPTH) & 1);
        const float4* row4 = (const float4*)(smem + SM_RING + slot * ROWB);
        float4 st[4];
        float d = 0.f;
#pragma unroll
        for (int c = 0; c < 4; c++) {
            st[c] = row4[tid + NTHR * c];
            if (MODE == 0)
                d += st[c].x * preg[c].x + st[c].y * preg[c].y
                   + st[c].z * preg[c].z + st[c].w * preg[c].w;
        }
        float tr;
        if (MODE == 1) {
            tr = xvec[row0 + r];
            __syncthreads();            // all LDS of this slot done before reissue
        } else {
            for (int o = 16; o; o >>= 1) d += __shfl_xor_sync(0xffffffffu, d, o);
            if ((tid & 31) == 0) wred[(r & 1) * 16 + (tid >> 5)] = d;
            __syncthreads();
        }
        if (tid == 0 && r + RDEPTH < nrows) {
            uint32_t mb = smb + SM_MBAR + slot * 16;   // slot(u+RDEPTH) == slot(u)
            MB_EXPECT(mb, ROWB);
            BULK_LD(smb + SM_RING + slot * ROWB,
                    (const void*)(H + (size_t)(row0 + r + RDEPTH) * NN), (uint32_t)ROWB, mb);
        }
        if (MODE == 0) {
            tr = 0.f;
#pragma unroll
            for (int w = 0; w < 16; w++) tr += wred[(r & 1) * 16 + w];
            if (tid == 0) smt[r] = tr;
        }
#pragma unroll
        for (int c = 0; c < 4; c++) {
            apa[c].x += tr * st[c].x; apa[c].y += tr * st[c].y;
            apa[c].z += tr * st[c].z; apa[c].w += tr * st[c].w;
        }
        ta += tr * tr;
    }
    gq += (unsigned)nrows;
    return ta;
}

// phase B: slab reduce over own columns + vector update (or setup init)
__device__ __forceinline__ void phaseB(char* smem, int tid, int bid, int c0, int nc,
                                       float alpha, bool setup) {
    float* sgp = (float*)(smem + SM_GPART);
    float* sred = (float*)(smem + SM_SRED);
    int g = tid >> 6, tc = tid & 63;
    float part = 0.f;
    if (tc < nc) {
        for (int cs = g; cs < NCTA; cs += 8) part += g_slab[(size_t)cs * NN + c0 + tc];
    }
    sgp[g * 64 + tc] = part;
    __syncthreads();
    if (tid < nc) {
        float ap = 0.f;
#pragma unroll
        for (int gg = 0; gg < 8; gg++) ap += sgp[gg * 64 + tid];
        int j = c0 + tid;
        float rn;
        if (setup) {
            g_v[j] = 0.f;
            g_r[j] = ap;      // r = b
            rn = ap;
        } else {
            g_v[j] += alpha * g_p[j];
            rn = g_r[j] - alpha * ap;
            g_r[j] = rn;
        }
        sred[tid] = rn * rn;
    }
    __syncthreads();
    if (tid == 0) {
        float s = 0.f;
        for (int i = 0; i < nc; i++) s += sred[i];
        g_rspart[bid] = s;
    }
}

// ---------------------------------------------------------------------------
// The persistent CG kernel: setup + 32 iterations; q_hat accumulated in smem.
// ---------------------------------------------------------------------------
__global__ void __launch_bounds__(NTHR, 1) cgm_persistent(const float* __restrict__ H,
                                                          const float* __restrict__ x) {
    extern __shared__ char smem[];
    int tid = threadIdx.x, bid = blockIdx.x;
    uint32_t smb = sm_u32(smem);
    float* smt = (float*)(smem + SM_T);
    float* smqh = (float*)(smem + SM_QH);
    if (tid == 0) {
        for (int s = 0; s < RDEPTH; s++) MB_INIT(smb + SM_MBAR + s * 16, 1);
    }
    if (tid < 64) smqh[tid] = 0.f;
    __syncthreads();
    unsigned base_gen = g_flags[bid];    // all flags equal at launch (monotone)
    unsigned barn = 0;
    unsigned gq = 0;

    int row0, nrows;
    if (bid < 52) { row0 = bid * 56; nrows = 56; }
    else          { row0 = 2912 + (bid - 52) * 55; nrows = 55; }
    int c0 = row0, nc = nrows;           // same partition for columns

    float4 apa[4], preg[4];
    float rs = 0.f;

    // ---- setup: b = H^T x (rank-1 streaming), then r=b, v=0, rs0 partials ----
    run_pass<1>(H, smem, smb, tid, row0, nrows, gq, preg, apa, x);
    {
        float4* slab4 = (float4*)(g_slab + (size_t)bid * NN);
#pragma unroll
        for (int c = 0; c < 4; c++) slab4[tid + NTHR * c] = apa[c];
    }
    grid_bar(tid, bid, base_gen + (++barn));
    phaseB(smem, tid, bid, c0, nc, 0.f, true);
    grid_bar(tid, bid, base_gen + (++barn));

    for (int it = 0; it < NITER; it++) {
        // ---- A: beta (redundant, fixed order), p update (registers + gmem) ----
        float rs_new = 0.f;
        for (int c = 0; c < NCTA; c++) rs_new += g_rspart[c];
        float beta = (it == 0) ? 0.f : rs_new / (rs + EPSF);
        rs = rs_new;
#pragma unroll
        for (int c = 0; c < 4; c++) {
            float4 rr = ((const float4*)g_r)[tid + NTHR * c];
            if (it == 0) preg[c] = rr;
            else preg[c] = make_float4(rr.x + beta * preg[c].x, rr.y + beta * preg[c].y,
                                       rr.z + beta * preg[c].z, rr.w + beta * preg[c].w);
            ((float4*)g_p)[tid + NTHR * c] = preg[c];
        }
        // ---- matvec: slab partials of H^T(Hp), tt partials, smem t ----
        float ta = run_pass<0>(H, smem, smb, tid, row0, nrows, gq, preg, apa, nullptr);
        {
            float4* slab4 = (float4*)(g_slab + (size_t)bid * NN);
#pragma unroll
            for (int c = 0; c < 4; c++) slab4[tid + NTHR * c] = apa[c];
        }
        if (tid == 0) g_ttpart[bid] = ta;
        grid_bar(tid, bid, base_gen + (++barn));

        // ---- B: alpha (redundant), qh += alpha*t, Ap reduce + v,r + rs ----
        float tt = 0.f;
        for (int c = 0; c < NCTA; c++) tt += g_ttpart[c];
        float alpha = rs / (tt + EPSF);
        if (tid < nrows) smqh[tid] += alpha * smt[tid];
        phaseB(smem, tid, bid, c0, nc, alpha, false);
        grid_bar(tid, bid, base_gen + (++barn));
    }

    // ---- final: write accumulated q_hat (== H v up to fp rounding) ----
    if (tid < nrows) g_qh[row0 + tid] = smqh[tid];
}

// ---------------------------------------------------------------------------
// metrics / fft / finalize / output (unchanged semantics)
// ---------------------------------------------------------------------------
__global__ void metrics_partial_kernel(const float* __restrict__ x,
                                       const float* __restrict__ qt,
                                       const float* __restrict__ vt) {
    int j = blockIdx.x * 128 + threadIdx.x;
    float qh = g_qh[j], vv = g_v[j];
    float qtj = qt[j], vtj = vt[j];
    float d0 = qh - x[j];
    float d1 = qh - qtj;
    float d2 = vv - vtj;
    float vals[7] = { d0 * d0, fabsf(d1), d1 * d1, qtj * qtj,
                      fabsf(d2), d2 * d2, vtj * vtj };
    __shared__ float sh4[4];
#pragma unroll
    for (int s = 0; s < 7; s++) {
        float d = vals[s];
        for (int o = 16; o; o >>= 1) d += __shfl_down_sync(0xffffffffu, d, o);
        if ((threadIdx.x & 31) == 0) sh4[threadIdx.x >> 5] = d;
        __syncthreads();
        if (threadIdx.x == 0)
            g_mpart[blockIdx.x * 8 + s] = sh4[0] + sh4[1] + sh4[2] + sh4[3];
        __syncthreads();
    }
}

__global__ void fft_metrics_kernel(const float* __restrict__ qt,
                                   const float* __restrict__ vt) {
    __shared__ float2 Z[4096];
    __shared__ float red[1024];
    int mode = blockIdx.x;
    int tid = threadIdx.x;

    for (int n = tid; n < 4096; n += 1024) {
        int i0 = 2 * n, i1 = 2 * n + 1;
        float a, b;
        if (mode == 0)      { a = g_qh[i0] - qt[i0]; b = g_qh[i1] - qt[i1]; }
        else if (mode == 1) { a = qt[i0];            b = qt[i1]; }
        else if (mode == 2) { a = g_v[i0] - vt[i0];  b = g_v[i1] - vt[i1]; }
        else                { a = vt[i0];            b = vt[i1]; }
        int r = (int)(__brev((unsigned)n) >> 20);
        Z[r] = make_float2(a, b);
    }
    __syncthreads();

    for (int half = 1; half < 4096; half <<= 1) {
        for (int i = tid; i < 2048; i += 1024) {
            int pos = i & (half - 1);
            int idx1 = ((i ^ pos) << 1) | pos;
            int idx2 = idx1 + half;
            float s, c;
            sincospif((float)pos / (float)half, &s, &c);
            float2 z2 = Z[idx2];
            float2 t = make_float2(c * z2.x + s * z2.y, c * z2.y - s * z2.x);
            float2 z1 = Z[idx1];
            Z[idx2] = make_float2(z1.x - t.x, z1.y - t.y);
            Z[idx1] = make_float2(z1.x + t.x, z1.y + t.y);
        }
        __syncthreads();
    }

    float sabs = 0.f, ssq = 0.f;
    for (int k = tid; k <= 4096; k += 1024) {
        float2 Zk = Z[k & 4095];
        float2 Zm = Z[(4096 - k) & 4095];
        float2 Zmc = make_float2(Zm.x, -Zm.y);
        float2 Fe = make_float2(0.5f * (Zk.x + Zmc.x), 0.5f * (Zk.y + Zmc.y));
        float2 Fd = make_float2(Zk.x - Zmc.x, Zk.y - Zmc.y);
        float2 Fo = make_float2(0.5f * Fd.y, -0.5f * Fd.x);
        float s, c;
        sincospif((float)k / 4096.0f, &s, &c);
        float Xr = Fe.x + (c * Fo.x + s * Fo.y);
        float Xi = Fe.y + (c * Fo.y - s * Fo.x);
        float m2 = Xr * Xr + Xi * Xi;
        sabs += sqrtf(m2);
        ssq += m2;
    }
    red[tid] = sabs;
    __syncthreads();
    for (int s = 512; s > 0; s >>= 1) {
        if (tid < s) red[tid] += red[tid + s];
        __syncthreads();
    }
    if (tid == 0) g_fftsum[2 * mode] = red[0];
    __syncthreads();
    red[tid] = ssq;
    __syncthreads();
    for (int s = 512; s > 0; s >>= 1) {
        if (tid < s) red[tid] += red[tid + s];
        __syncthreads();
    }
    if (tid == 0) g_fftsum[2 * mode + 1] = red[0];
}

__global__ void finalize_kernel(float* __restrict__ out, int out_size) {
    if (threadIdx.x != 0 || blockIdx.x != 0) return;
    float s[7];
    for (int k = 0; k < 7; k++) {
        float a = 0.f;
        for (int b = 0; b < 64; b++) a += g_mpart[b * 8 + k];
        s[k] = a;
    }
    float res[11];
    res[0]  = sqrtf(s[0]);
    res[1]  = s[1] / (float)NN;
    res[2]  = s[2] / (s[3] + EPSF);
    res[3]  = s[4] / (float)NN;
    res[4]  = s[5] / (s[6] + EPSF);
    res[5]  = s[2] / (float)NN;
    res[6]  = s[5] / (float)NN;
    res[7]  = g_fftsum[0] / 4097.0f;
    res[8]  = g_fftsum[1] / (g_fftsum[3] + EPSF);
    res[9]  = g_fftsum[4] / 4097.0f;
    res[10] = g_fftsum[5] / (g_fftsum[7] + EPSF);
    for (int k = 0; k < 11; k++)
        if (NN + k < out_size) out[NN + k] = res[k];
}

__global__ void copy_v_kernel(float* __restrict__ out, int out_size) {
    int j = blockIdx.x * 128 + threadIdx.x;
    if (j >= out_size) return;
    if (j < NN) out[j] = g_v[j];
    else if (j >= NN + 11) out[j] = 0.f;
}

extern "C" void kernel_launch(void* const* d_in, const int* in_sizes, int n_in,
                              void* d_out, int out_size) {
    const float* H = nullptr;
    const float* x = nullptr;
    const float* vt = nullptr;
    const float* qt = nullptr;
    int vecseen = 0;
    for (int i = 0; i < n_in; i++) {
        if (in_sizes[i] == NN * NN) {
            H = (const float*)d_in[i];
        } else if (in_sizes[i] == NN) {
            if (vecseen == 0)      x  = (const float*)d_in[i];
            else if (vecseen == 1) vt = (const float*)d_in[i];
            else if (vecseen == 2) qt = (const float*)d_in[i];
            vecseen++;
        }
    }
    float* out = (float*)d_out;

    cudaFuncSetAttribute(cgm_persistent, cudaFuncAttributeMaxDynamicSharedMemorySize,
                         SMEM_TOTAL);

    cgm_persistent<<<NCTA, NTHR, SMEM_TOTAL>>>(H, x);

    metrics_partial_kernel<<<64, 128>>>(x, qt, vt);
    fft_metrics_kernel<<<4, 1024>>>(qt, vt);
    finalize_kernel<<<1, 32>>>(out, out_size);
    {
        int nblk = (out_size + 127) / 128;
        if (nblk < 1) nblk = 1;
        copy_v_kernel<<<nblk, 128>>>(out, out_size);
    }
}

// round 7
// speedup vs baseline: 1.1932x; 1.1932x over previous
#include <cuda_runtime.h>
#include <cstdint>
#include <math.h>

#define NN 8192
#define EPSF 1e-20f
#define NITER 32
#define NCTA 148
#define NTHR 512
#define ROWB 32768               // bytes per H row
#define RDEPTH 4                 // TMA ring slots (power of 2)

// dynamic smem layout
#define SM_MBAR 0                // 4 mbarriers, 16B stride
#define SM_WRED 128              // 2 x 16 warp partials (double-buffered)
#define SM_GPART 1024            // 512 floats (phase-B group partials)
#define SM_SRED 3072             // 64 floats (phase-B rs partials)
#define SM_T    3328             // 56 floats: this CTA's t_r = (Hp)_row
#define SM_QH   3584             // 56 floats: incremental q_hat for own rows
#define SM_RING 4096             // RDEPTH x 32768 row buffers
#define SMEM_TOTAL (SM_RING + RDEPTH * ROWB)

// ---- device scratch (no allocations allowed) ----
__device__ float g_slab[NCTA * NN];     // 4.85 MB per-CTA Ap partial slabs
__device__ float g_ttpart[NCTA];
__device__ float g_rspart[NCTA];
__device__ float g_r[NN], g_p[NN], g_v[NN], g_qh[NN];
__device__ float g_mpart[64 * 8];
__device__ float g_fftsum[8];
__device__ unsigned g_flags[NCTA];      // grid-barrier flags (monotone across replays)

// ---------------- PTX helpers ----------------
__device__ __forceinline__ uint32_t sm_u32(const void* p) {
    uint32_t a;
    asm("{ .reg .u64 t; cvta.to.shared.u64 t, %1; cvt.u32.u64 %0, t; }" : "=r"(a) : "l"(p));
    return a;
}
#define MB_INIT(a, c) \
    asm volatile("mbarrier.init.shared.b64 [%0], %1;" :: "r"(a), "r"(c) : "memory")
#define MB_EXPECT(a, b) \
    asm volatile("mbarrier.arrive.expect_tx.shared.b64 _, [%0], %1;" :: "r"(a), "r"(b) : "memory")
#define BULK_LD(dst, src, sz, mb) \
    asm volatile("cp.async.bulk.shared::cta.global.mbarrier::complete_tx::bytes [%0], [%1], %2, [%3];" \
                 :: "r"(dst), "l"(src), "r"(sz), "r"(mb) : "memory")

__device__ __forceinline__ void mb_wait(uint32_t mbar, uint32_t parity) {
    uint32_t done;
    do {
        asm volatile("{ .reg .pred p; mbarrier.try_wait.parity.acquire.cta.shared::cta.b64 p, [%1], %2; "
                     "selp.b32 %0, 1, 0, p; }" : "=r"(done) : "r"(mbar), "r"(parity) : "memory");
    } while (!done);
}

__device__ __forceinline__ void grid_bar(int tid, int bid, unsigned gen) {
    __syncthreads();
    if (tid == 0)
        asm volatile("st.global.release.gpu.u32 [%0], %1;" :: "l"(&g_flags[bid]), "r"(gen) : "memory");
    if (tid < NCTA) {
        unsigned v;
        do {
            asm volatile("ld.global.acquire.gpu.u32 %0, [%1];" : "=r"(v) : "l"(&g_flags[tid]) : "memory");
        } while ((int)(v - gen) < 0);
    }
    __syncthreads();
}

// ---------------------------------------------------------------------------
// One streaming pass over this CTA's rows via the TMA ring.
// MODE 0: tr = dot(row, preg) -> apa += tr*row, ta += tr*tr, smem t[r] = tr
// MODE 1: tr = xvec[row]      -> apa += tr*row                (setup b = H^T x)
// ---------------------------------------------------------------------------
template<int MODE>
__device__ __forceinline__ float run_pass(const float* __restrict__ H, char* smem,
                                          uint32_t smb, int tid, int row0, int nrows,
                                          unsigned& gq, const float4* preg, float4* apa,
                                          const float* __restrict__ xvec) {
    float* wred = (float*)(smem + SM_WRED);
    float* smt  = (float*)(smem + SM_T);
#pragma unroll
    for (int c = 0; c < 4; c++) apa[c] = make_float4(0.f, 0.f, 0.f, 0.f);
    float ta = 0.f;
    if (tid == 0) {
        int npro = nrows < RDEPTH ? nrows : RDEPTH;
        for (int k = 0; k < npro; k++) {
            unsigned u = gq + k;
            uint32_t slot = u & (RDEPTH - 1);
            uint32_t mb = smb + SM_MBAR + slot * 16;
            MB_EXPECT(mb, ROWB);
            BULK_LD(smb + SM_RING + slot * ROWB,
                    (const void*)(H + (size_t)(row0 + k) * NN), (uint32_t)ROWB, mb);
        }
    }
    for (int r = 0; r < nrows; r++) {
        unsigned u = gq + r;
        uint32_t slot = u & (RDEPTH - 1);
        mb_wait(smb + SM_MBAR + slot * 16, (u >> 2) & 1);
        const float4* row4 = (const float4*)(smem + SM_RING + slot * ROWB);
        float4 st[4];
        float d = 0.f;
#pragma unroll
        for (int c = 0; c < 4; c++) {
            st[c] = row4[tid + NTHR * c];
            if (MODE == 0)
                d += st[c].x * preg[c].x + st[c].y * preg[c].y
                   + st[c].z * preg[c].z + st[c].w * preg[c].w;
        }
        float tr;
        if (MODE == 1) {
            tr = xvec[row0 + r];
            __syncthreads();            // all LDS of this slot done before reissue
        } else {
            for (int o = 16; o; o >>= 1) d += __shfl_xor_sync(0xffffffffu, d, o);
            if ((tid & 31) == 0) wred[(r & 1) * 16 + (tid >> 5)] = d;
            __syncthreads();
        }
        if (tid == 0 && r + RDEPTH < nrows) {
            uint32_t mb = smb + SM_MBAR + slot * 16;   // slot(u+RDEPTH) == slot(u)
            MB_EXPECT(mb, ROWB);
            BULK_LD(smb + SM_RING + slot * ROWB,
                    (const void*)(H + (size_t)(row0 + r + RDEPTH) * NN), (uint32_t)ROWB, mb);
        }
        if (MODE == 0) {
            tr = 0.f;
#pragma unroll
            for (int w = 0; w < 16; w++) tr += wred[(r & 1) * 16 + w];
            if (tid == 0) smt[r] = tr;
        }
#pragma unroll
        for (int c = 0; c < 4; c++) {
            apa[c].x += tr * st[c].x; apa[c].y += tr * st[c].y;
            apa[c].z += tr * st[c].z; apa[c].w += tr * st[c].w;
        }
        ta += tr * tr;
    }
    gq += (unsigned)nrows;
    return ta;
}

// phase B: slab reduce over own columns + vector update (or setup init)
__device__ __forceinline__ void phaseB(char* smem, int tid, int bid, int c0, int nc,
                                       float alpha, bool setup) {
    float* sgp = (float*)(smem + SM_GPART);
    float* sred = (float*)(smem + SM_SRED);
    int g = tid >> 6, tc = tid & 63;
    float part = 0.f;
    if (tc < nc) {
        for (int cs = g; cs < NCTA; cs += 8) part += g_slab[(size_t)cs * NN + c0 + tc];
    }
    sgp[g * 64 + tc] = part;
    __syncthreads();
    if (tid < nc) {
        float ap = 0.f;
#pragma unroll
        for (int gg = 0; gg < 8; gg++) ap += sgp[gg * 64 + tid];
        int j = c0 + tid;
        float rn;
        if (setup) {
            g_v[j] = 0.f;
            g_r[j] = ap;      // r = b
            rn = ap;
        } else {
            g_v[j] += alpha * g_p[j];
            rn = g_r[j] - alpha * ap;
            g_r[j] = rn;
        }
        sred[tid] = rn * rn;
    }
    __syncthreads();
    if (tid == 0) {
        float s = 0.f;
        for (int i = 0; i < nc; i++) s += sred[i];
        g_rspart[bid] = s;
    }
}

// ---------------------------------------------------------------------------
// The persistent CG kernel: setup + 32 iterations; q_hat accumulated in smem.
// ---------------------------------------------------------------------------
__global__ void __launch_bounds__(NTHR, 1) cgm_persistent(const float* __restrict__ H,
                                                          const float* __restrict__ x) {
    extern __shared__ char smem[];
    int tid = threadIdx.x, bid = blockIdx.x;
    uint32_t smb = sm_u32(smem);
    float* smt = (float*)(smem + SM_T);
    float* smqh = (float*)(smem + SM_QH);
    if (tid == 0) {
        for (int s = 0; s < RDEPTH; s++) MB_INIT(smb + SM_MBAR + s * 16, 1);
    }
    if (tid < 64) smqh[tid] = 0.f;
    __syncthreads();
    unsigned base_gen = g_flags[bid];    // all flags equal at launch (monotone)
    unsigned barn = 0;
    unsigned gq = 0;

    int row0, nrows;
    if (bid < 52) { row0 = bid * 56; nrows = 56; }
    else          { row0 = 2912 + (bid - 52) * 55; nrows = 55; }
    int c0 = row0, nc = nrows;           // same partition for columns

    float4 apa[4], preg[4];
    float rs = 0.f;

    // ---- setup: b = H^T x (rank-1 streaming), then r=b, v=0, rs0 partials ----
    run_pass<1>(H, smem, smb, tid, row0, nrows, gq, preg, apa, x);
    {
        float4* slab4 = (float4*)(g_slab + (size_t)bid * NN);
#pragma unroll
        for (int c = 0; c < 4; c++) slab4[tid + NTHR * c] = apa[c];
    }
    grid_bar(tid, bid, base_gen + (++barn));
    phaseB(smem, tid, bid, c0, nc, 0.f, true);
    grid_bar(tid, bid, base_gen + (++barn));

    for (int it = 0; it < NITER; it++) {
        // ---- A: beta (redundant, fixed order), p update (registers + gmem) ----
        float rs_new = 0.f;
        for (int c = 0; c < NCTA; c++) rs_new += g_rspart[c];
        float beta = (it == 0) ? 0.f : rs_new / (rs + EPSF);
        rs = rs_new;
#pragma unroll
        for (int c = 0; c < 4; c++) {
            float4 rr = ((const float4*)g_r)[tid + NTHR * c];
            if (it == 0) preg[c] = rr;
            else preg[c] = make_float4(rr.x + beta * preg[c].x, rr.y + beta * preg[c].y,
                                       rr.z + beta * preg[c].z, rr.w + beta * preg[c].w);
            ((float4*)g_p)[tid + NTHR * c] = preg[c];
        }
        // ---- matvec: slab partials of H^T(Hp), tt partials, smem t ----
        float ta = run_pass<0>(H, smem, smb, tid, row0, nrows, gq, preg, apa, nullptr);
        {
            float4* slab4 = (float4*)(g_slab + (size_t)bid * NN);
#pragma unroll
            for (int c = 0; c < 4; c++) slab4[tid + NTHR * c] = apa[c];
        }
        if (tid == 0) g_ttpart[bid] = ta;
        grid_bar(tid, bid, base_gen + (++barn));

        // ---- B: alpha (redundant), qh += alpha*t, Ap reduce + v,r + rs ----
        float tt = 0.f;
        for (int c = 0; c < NCTA; c++) tt += g_ttpart[c];
        float alpha = rs / (tt + EPSF);
        if (tid < nrows) smqh[tid] += alpha * smt[tid];
        phaseB(smem, tid, bid, c0, nc, alpha, false);
        grid_bar(tid, bid, base_gen + (++barn));
    }

    // ---- final: write accumulated q_hat (== H v up to fp rounding) ----
    if (tid < nrows) g_qh[row0 + tid] = smqh[tid];
}

// ---------------------------------------------------------------------------
// metrics / fft / finalize / output (unchanged semantics)
// ---------------------------------------------------------------------------
__global__ void metrics_partial_kernel(const float* __restrict__ x,
                                       const float* __restrict__ qt,
                                       const float* __restrict__ vt) {
    int j = blockIdx.x * 128 + threadIdx.x;
    float qh = g_qh[j], vv = g_v[j];
    float qtj = qt[j], vtj = vt[j];
    float d0 = qh - x[j];
    float d1 = qh - qtj;
    float d2 = vv - vtj;
    float vals[7] = { d0 * d0, fabsf(d1), d1 * d1, qtj * qtj,
                      fabsf(d2), d2 * d2, vtj * vtj };
    __shared__ float sh4[4];
#pragma unroll
    for (int s = 0; s < 7; s++) {
        float d = vals[s];
        for (int o = 16; o; o >>= 1) d += __shfl_down_sync(0xffffffffu, d, o);
        if ((threadIdx.x & 31) == 0) sh4[threadIdx.x >> 5] = d;
        __syncthreads();
        if (threadIdx.x == 0)
            g_mpart[blockIdx.x * 8 + s] = sh4[0] + sh4[1] + sh4[2] + sh4[3];
        __syncthreads();
    }
}

__global__ void fft_metrics_kernel(const float* __restrict__ qt,
                                   const float* __restrict__ vt) {
    __shared__ float2 Z[4096];
    __shared__ float red[1024];
    int mode = blockIdx.x;
    int tid = threadIdx.x;

    for (int n = tid; n < 4096; n += 1024) {
        int i0 = 2 * n, i1 = 2 * n + 1;
        float a, b;
        if (mode == 0)      { a = g_qh[i0] - qt[i0]; b = g_qh[i1] - qt[i1]; }
        else if (mode == 1) { a = qt[i0];            b = qt[i1]; }
        else if (mode == 2) { a = g_v[i0] - vt[i0];  b = g_v[i1] - vt[i1]; }
        else                { a = vt[i0];            b = vt[i1]; }
        int r = (int)(__brev((unsigned)n) >> 20);
        Z[r] = make_float2(a, b);
    }
    __syncthreads();

    for (int half = 1; half < 4096; half <<= 1) {
        for (int i = tid; i < 2048; i += 1024) {
            int pos = i & (half - 1);
            int idx1 = ((i ^ pos) << 1) | pos;
            int idx2 = idx1 + half;
            float s, c;
            sincospif((float)pos / (float)half, &s, &c);
            float2 z2 = Z[idx2];
            float2 t = make_float2(c * z2.x + s * z2.y, c * z2.y - s * z2.x);
            float2 z1 = Z[idx1];
            Z[idx2] = make_float2(z1.x - t.x, z1.y - t.y);
            Z[idx1] = make_float2(z1.x + t.x, z1.y + t.y);
        }
        __syncthreads();
    }

    float sabs = 0.f, ssq = 0.f;
    for (int k = tid; k <= 4096; k += 1024) {
        float2 Zk = Z[k & 4095];
        float2 Zm = Z[(4096 - k) & 4095];
        float2 Zmc = make_float2(Zm.x, -Zm.y);
        float2 Fe = make_float2(0.5f * (Zk.x + Zmc.x), 0.5f * (Zk.y + Zmc.y));
        float2 Fd = make_float2(Zk.x - Zmc.x, Zk.y - Zmc.y);
        float2 Fo = make_float2(0.5f * Fd.y, -0.5f * Fd.x);
        float s, c;
        sincospif((float)k / 4096.0f, &s, &c);
        float Xr = Fe.x + (c * Fo.x + s * Fo.y);
        float Xi = Fe.y + (c * Fo.y - s * Fo.x);
        float m2 = Xr * Xr + Xi * Xi;
        sabs += sqrtf(m2);
        ssq += m2;
    }
    red[tid] = sabs;
    __syncthreads();
    for (int s = 512; s > 0; s >>= 1) {
        if (tid < s) red[tid] += red[tid + s];
        __syncthreads();
    }
    if (tid == 0) g_fftsum[2 * mode] = red[0];
    __syncthreads();
    red[tid] = ssq;
    __syncthreads();
    for (int s = 512; s > 0; s >>= 1) {
        if (tid < s) red[tid] += red[tid + s];
        __syncthreads();
    }
    if (tid == 0) g_fftsum[2 * mode + 1] = red[0];
}

__global__ void finalize_kernel(float* __restrict__ out, int out_size) {
    if (threadIdx.x != 0 || blockIdx.x != 0) return;
    float s[7];
    for (int k = 0; k < 7; k++) {
        float a = 0.f;
        for (int b = 0; b < 64; b++) a += g_mpart[b * 8 + k];
        s[k] = a;
    }
    float res[11];
    res[0]  = sqrtf(s[0]);
    res[1]  = s[1] / (float)NN;
    res[2]  = s[2] / (s[3] + EPSF);
    res[3]  = s[4] / (float)NN;
    res[4]  = s[5] / (s[6] + EPSF);
    res[5]  = s[2] / (float)NN;
    res[6]  = s[5] / (float)NN;
    res[7]  = g_fftsum[0] / 4097.0f;
    res[8]  = g_fftsum[1] / (g_fftsum[3] + EPSF);
    res[9]  = g_fftsum[4] / 4097.0f;
    res[10] = g_fftsum[5] / (g_fftsum[7] + EPSF);
    for (int k = 0; k < 11; k++)
        if (NN + k < out_size) out[NN + k] = res[k];
}

__global__ void copy_v_kernel(float* __restrict__ out, int out_size) {
    int j = blockIdx.x * 128 + threadIdx.x;
    if (j >= out_size) return;
    if (j < NN) out[j] = g_v[j];
    else if (j >= NN + 11) out[j] = 0.f;
}

extern "C" void kernel_launch(void* const* d_in, const int* in_sizes, int n_in,
                              void* d_out, int out_size) {
    const float* H = nullptr;
    const float* x = nullptr;
    const float* vt = nullptr;
    const float* qt = nullptr;
    int vecseen = 0;
    for (int i = 0; i < n_in; i++) {
        if (in_sizes[i] == NN * NN) {
            H = (const float*)d_in[i];
        } else if (in_sizes[i] == NN) {
            if (vecseen == 0)      x  = (const float*)d_in[i];
            else if (vecseen == 1) vt = (const float*)d_in[i];
            else if (vecseen == 2) qt = (const float*)d_in[i];
            vecseen++;
        }
    }
    float* out = (float*)d_out;

    cudaFuncSetAttribute(cgm_persistent, cudaFuncAttributeMaxDynamicSharedMemorySize,
                         SMEM_TOTAL);

    cgm_persistent<<<NCTA, NTHR, SMEM_TOTAL>>>(H, x);

    metrics_partial_kernel<<<64, 128>>>(x, qt, vt);
    fft_metrics_kernel<<<4, 1024>>>(qt, vt);
    finalize_kernel<<<1, 32>>>(out, out_size);
    {
        int nblk = (out_size + 127) / 128;
        if (nblk < 1) nblk = 1;
        copy_v_kernel<<<nblk, 128>>>(out, out_size);
    }
}